// round 1
// baseline (speedup 1.0000x reference)
#include <cuda_runtime.h>

#define BB 16
#define NN 1024
#define DD 1024   // D2H
#define UU 512
#define TOK (BB * NN)
#define UCHUNKS 8
#define UC (UU / UCHUNKS)   // 64

// Scratch (no device allocation allowed; must be rewritten every launch since
// graph replays reuse them — no reliance on zero-init).
__device__ float g_ph[UCHUNKS * DD];
__device__ float g_pm[UCHUNKS * DD];
__device__ float g_vh[DD];
__device__ float g_vm[DD];
__device__ float g_const;
__device__ float g_sH[TOK];
__device__ float g_sM[TOK];

// ---------------------------------------------------------------------------
// Stage 1: partial v_h/v_m.  v_h[d] = sum_u W_h[u,d] * w_out[u]
// grid (DD/128, UCHUNKS), block 128.  Coalesced reads of W rows; each thread
// accumulates 64 u's (unrolled -> deep MLP, hides DRAM latency).
// ---------------------------------------------------------------------------
__global__ void k_vec_partial(const float* __restrict__ Wh,
                              const float* __restrict__ Wm,
                              const float* __restrict__ wout) {
    int d  = blockIdx.x * 128 + threadIdx.x;
    int u0 = blockIdx.y * UC;
    float ah = 0.f, am = 0.f;
#pragma unroll 16
    for (int i = 0; i < UC; ++i) {
        float w = __ldg(&wout[u0 + i]);
        ah = fmaf(Wh[(size_t)(u0 + i) * DD + d], w, ah);
        am = fmaf(Wm[(size_t)(u0 + i) * DD + d], w, am);
    }
    g_ph[blockIdx.y * DD + d] = ah;
    g_pm[blockIdx.y * DD + d] = am;
}

// Stage 2a: fold the 8 partials.  grid DD/256, block 256.
__global__ void k_vec_reduce() {
    int d = blockIdx.x * 256 + threadIdx.x;
    float ah = 0.f, am = 0.f;
#pragma unroll
    for (int c = 0; c < UCHUNKS; ++c) {
        ah += g_ph[c * DD + d];
        am += g_pm[c * DD + d];
    }
    g_vh[d] = ah;
    g_vm[d] = am;
}

// Stage 2b: g_const = (b_h + b_m) . w_out + b_out.  One block, UU threads.
__global__ void k_const(const float* __restrict__ bh,
                        const float* __restrict__ bm,
                        const float* __restrict__ wout,
                        const float* __restrict__ bout) {
    __shared__ float red[UU / 32];
    int t = threadIdx.x;
    float acc = (bh[t] + bm[t]) * wout[t];
#pragma unroll
    for (int o = 16; o > 0; o >>= 1)
        acc += __shfl_down_sync(0xffffffffu, acc, o);
    if ((t & 31) == 0) red[t >> 5] = acc;
    __syncthreads();
    if (t < UU / 32) {
        acc = red[t];
#pragma unroll
        for (int o = (UU / 64); o > 0; o >>= 1)
            acc += __shfl_down_sync((1u << (UU / 32)) - 1u, acc, o);
        if (t == 0) g_const = acc + bout[0];
    }
}

// ---------------------------------------------------------------------------
// Stage 3: per-token dual dot product.  One block (256 thr) per token row.
// sH[row] = x[row,:].v_h ; sM[row] = x[row,:].v_m.  Reads x once (64 MB).
// ---------------------------------------------------------------------------
__global__ void k_row(const float* __restrict__ x) {
    int row = blockIdx.x;
    int t   = threadIdx.x;  // 256 threads, 4 floats each = 1024
    const float4* xr  = reinterpret_cast<const float4*>(x + (size_t)row * DD);
    const float4* vh4 = reinterpret_cast<const float4*>(g_vh);
    const float4* vm4 = reinterpret_cast<const float4*>(g_vm);

    float4 xv = xr[t];
    float4 h  = vh4[t];
    float4 m  = vm4[t];
    float ah = xv.x * h.x + xv.y * h.y + xv.z * h.z + xv.w * h.w;
    float am = xv.x * m.x + xv.y * m.y + xv.z * m.z + xv.w * m.w;

    __shared__ float sh[8], sm[8];
#pragma unroll
    for (int o = 16; o > 0; o >>= 1) {
        ah += __shfl_down_sync(0xffffffffu, ah, o);
        am += __shfl_down_sync(0xffffffffu, am, o);
    }
    if ((t & 31) == 0) { sh[t >> 5] = ah; sm[t >> 5] = am; }
    __syncthreads();
    if (t < 8) {
        ah = sh[t];
        am = sm[t];
#pragma unroll
        for (int o = 4; o > 0; o >>= 1) {
            ah += __shfl_down_sync(0x000000ffu, ah, o);
            am += __shfl_down_sync(0x000000ffu, am, o);
        }
        if (t == 0) { g_sH[row] = ah; g_sM[row] = am; }
    }
}

// ---------------------------------------------------------------------------
// Stage 4: scores[b,i,j] = sH[b,i] + sM[b,j] + const.  One block (256 thr)
// per output row; float4 stores (64 MB write, the bandwidth floor).
// ---------------------------------------------------------------------------
__global__ void k_out(float* __restrict__ out) {
    int gi = blockIdx.x;           // b*NN + i
    int b  = gi >> 10;             // NN = 1024
    float base = g_sH[gi] + g_const;
    const float4* mr = reinterpret_cast<const float4*>(g_sM + (size_t)b * NN);
    float4* orow = reinterpret_cast<float4*>(out + (size_t)gi * NN);
    float4 m = mr[threadIdx.x];
    orow[threadIdx.x] = make_float4(base + m.x, base + m.y, base + m.z, base + m.w);
}

extern "C" void kernel_launch(void* const* d_in, const int* in_sizes, int n_in,
                              void* d_out, int out_size) {
    const float* x    = (const float*)d_in[0];
    const float* Wh   = (const float*)d_in[1];
    const float* bh   = (const float*)d_in[2];
    const float* Wm   = (const float*)d_in[3];
    const float* bm   = (const float*)d_in[4];
    const float* wout = (const float*)d_in[5];
    const float* bout = (const float*)d_in[6];
    float* out = (float*)d_out;

    k_vec_partial<<<dim3(DD / 128, UCHUNKS), 128>>>(Wh, Wm, wout);
    k_vec_reduce<<<DD / 256, 256>>>();
    k_const<<<1, UU>>>(bh, bm, wout, bout);
    k_row<<<TOK, 256>>>(x);
    k_out<<<TOK, 256>>>(out);
}

// round 2
// speedup vs baseline: 1.1479x; 1.1479x over previous
#include <cuda_runtime.h>

#define BB 16
#define NN 1024
#define DD 1024   // D2H
#define UU 512
#define TOK (BB * NN)
#define UCHUNKS 8
#define UC (UU / UCHUNKS)   // 64
#define ROWS_PER_BLK 8

// Scratch (no device allocation allowed; rewritten every launch — graph
// replays reuse these, so no reliance on zero-init).
__device__ float g_ph[UCHUNKS * DD];
__device__ float g_pm[UCHUNKS * DD];
__device__ float g_vh[DD];
__device__ float g_vm[DD];
__device__ float g_const;
__device__ float g_sH[TOK];
__device__ float g_sM[TOK];

// ---------------------------------------------------------------------------
// Stage 1: partial v_h/v_m.  v_h[d] = sum_u W_h[u,d] * w_out[u]
// grid (DD/128, UCHUNKS), block 128.  Coalesced reads of W rows.
// ---------------------------------------------------------------------------
__global__ void k_vec_partial(const float* __restrict__ Wh,
                              const float* __restrict__ Wm,
                              const float* __restrict__ wout) {
    int d  = blockIdx.x * 128 + threadIdx.x;
    int u0 = blockIdx.y * UC;
    float ah = 0.f, am = 0.f;
#pragma unroll 16
    for (int i = 0; i < UC; ++i) {
        float w = __ldg(&wout[u0 + i]);
        ah = fmaf(Wh[(size_t)(u0 + i) * DD + d], w, ah);
        am = fmaf(Wm[(size_t)(u0 + i) * DD + d], w, am);
    }
    g_ph[blockIdx.y * DD + d] = ah;
    g_pm[blockIdx.y * DD + d] = am;
}

// ---------------------------------------------------------------------------
// Stage 2 (fused): blocks 0..3 fold the 8 partials into v_h/v_m (256 d each);
// block 4 computes g_const = (b_h + b_m) . w_out + b_out.
// ---------------------------------------------------------------------------
__global__ void k_finish(const float* __restrict__ bh,
                         const float* __restrict__ bm,
                         const float* __restrict__ wout,
                         const float* __restrict__ bout) {
    int t = threadIdx.x;
    if (blockIdx.x < 4) {
        int d = blockIdx.x * 256 + t;
        float ah = 0.f, am = 0.f;
#pragma unroll
        for (int c = 0; c < UCHUNKS; ++c) {
            ah += g_ph[c * DD + d];
            am += g_pm[c * DD + d];
        }
        g_vh[d] = ah;
        g_vm[d] = am;
    } else {
        // const reduction: 256 threads, each covers 2 u's
        __shared__ float red[8];
        float acc = (bh[t] + bm[t]) * wout[t]
                  + (bh[t + 256] + bm[t + 256]) * wout[t + 256];
#pragma unroll
        for (int o = 16; o > 0; o >>= 1)
            acc += __shfl_down_sync(0xffffffffu, acc, o);
        if ((t & 31) == 0) red[t >> 5] = acc;
        __syncthreads();
        if (t < 8) {
            acc = red[t];
#pragma unroll
            for (int o = 4; o > 0; o >>= 1)
                acc += __shfl_down_sync(0x000000ffu, acc, o);
            if (t == 0) g_const = acc + bout[0];
        }
    }
}

// ---------------------------------------------------------------------------
// Stage 3: warp-per-row dual dot product.  Each lane loads 8 float4 of x
// (MLP=8), v vectors are L1-resident.  Pure shfl reduction, no smem/bar.
// Block 256 = 8 warps = 8 rows; grid TOK/8 = 2048.
// ---------------------------------------------------------------------------
__global__ void k_row(const float* __restrict__ x) {
    int row  = (blockIdx.x * blockDim.x + threadIdx.x) >> 5;
    int lane = threadIdx.x & 31;
    const float4* xr  = reinterpret_cast<const float4*>(x + (size_t)row * DD);
    const float4* vh4 = reinterpret_cast<const float4*>(g_vh);
    const float4* vm4 = reinterpret_cast<const float4*>(g_vm);

    float ah = 0.f, am = 0.f;
#pragma unroll
    for (int i = 0; i < 8; ++i) {
        int idx = lane + 32 * i;
        float4 xv = xr[idx];
        float4 h  = vh4[idx];
        float4 m  = vm4[idx];
        ah = fmaf(xv.x, h.x, fmaf(xv.y, h.y, fmaf(xv.z, h.z, fmaf(xv.w, h.w, ah))));
        am = fmaf(xv.x, m.x, fmaf(xv.y, m.y, fmaf(xv.z, m.z, fmaf(xv.w, m.w, am))));
    }
#pragma unroll
    for (int o = 16; o > 0; o >>= 1) {
        ah += __shfl_xor_sync(0xffffffffu, ah, o);
        am += __shfl_xor_sync(0xffffffffu, am, o);
    }
    if (lane == 0) { g_sH[row] = ah; g_sM[row] = am; }
}

// ---------------------------------------------------------------------------
// Stage 4: scores[b,i,j] = sH[b,i] + sM[b,j] + const.  8 rows per block:
// sM float4 loaded once per thread (L2 hit), then 8 independent STG.128.
// grid TOK/8 = 2048, block 256.
// ---------------------------------------------------------------------------
__global__ void k_out(float* __restrict__ out) {
    int i0 = blockIdx.x * ROWS_PER_BLK;    // global row base (b*NN + i)
    int b  = i0 >> 10;                     // NN = 1024; 8 | NN so same batch
    int t  = threadIdx.x;

    float4 m = reinterpret_cast<const float4*>(g_sM + (size_t)b * NN)[t];
    float  c = g_const;

    // vector-load the 8 sH values
    float4 h0 = reinterpret_cast<const float4*>(g_sH + i0)[0];
    float4 h1 = reinterpret_cast<const float4*>(g_sH + i0)[1];
    float base[ROWS_PER_BLK] = {h0.x + c, h0.y + c, h0.z + c, h0.w + c,
                                h1.x + c, h1.y + c, h1.z + c, h1.w + c};
#pragma unroll
    for (int r = 0; r < ROWS_PER_BLK; ++r) {
        reinterpret_cast<float4*>(out + (size_t)(i0 + r) * NN)[t] =
            make_float4(base[r] + m.x, base[r] + m.y, base[r] + m.z, base[r] + m.w);
    }
}

extern "C" void kernel_launch(void* const* d_in, const int* in_sizes, int n_in,
                              void* d_out, int out_size) {
    const float* x    = (const float*)d_in[0];
    const float* Wh   = (const float*)d_in[1];
    const float* bh   = (const float*)d_in[2];
    const float* Wm   = (const float*)d_in[3];
    const float* bm   = (const float*)d_in[4];
    const float* wout = (const float*)d_in[5];
    const float* bout = (const float*)d_in[6];
    float* out = (float*)d_out;

    k_vec_partial<<<dim3(DD / 128, UCHUNKS), 128>>>(Wh, Wm, wout);
    k_finish<<<5, 256>>>(bh, bm, wout, bout);
    k_row<<<TOK / 8, 256>>>(x);
    k_out<<<TOK / ROWS_PER_BLK, 256>>>(out);
}

// round 3
// speedup vs baseline: 1.4029x; 1.2221x over previous
#include <cuda_runtime.h>

#define BB 16
#define NN 1024
#define DD 1024   // D2H
#define UU 512
#define TOK (BB * NN)
#define UCHUNKS 8
#define UC (UU / UCHUNKS)          // 64
#define ROW_BLOCKS (TOK / 8)       // 2048 (8 rows per block, warp per row)
#define OUT_BLOCKS (TOK / 8)       // 2048 (8 rows per block)
#define RB_PER_BATCH (NN / 8)      // 128 row-blocks per batch

// Scratch (no device allocation allowed; rewritten every launch).
__device__ float g_ph[UCHUNKS * DD];
__device__ float g_pm[UCHUNKS * DD];
__device__ float g_vh[DD];
__device__ float g_vm[DD];
__device__ float g_const;
__device__ float g_sH[TOK];
__device__ float g_sM[TOK];
__device__ int   g_done[BB];

// ---------------------------------------------------------------------------
// Stage 0: zero the per-batch completion counters (graph replays reuse them).
// ---------------------------------------------------------------------------
__global__ void k_zero() {
    if (threadIdx.x < BB) g_done[threadIdx.x] = 0;
}

// ---------------------------------------------------------------------------
// Stage 1: partial v_h/v_m.  v_h[d] = sum_u W_h[u,d] * w_out[u]
// ---------------------------------------------------------------------------
__global__ void k_vec_partial(const float* __restrict__ Wh,
                              const float* __restrict__ Wm,
                              const float* __restrict__ wout) {
    int d  = blockIdx.x * 128 + threadIdx.x;
    int u0 = blockIdx.y * UC;
    float ah = 0.f, am = 0.f;
#pragma unroll 16
    for (int i = 0; i < UC; ++i) {
        float w = __ldg(&wout[u0 + i]);
        ah = fmaf(Wh[(size_t)(u0 + i) * DD + d], w, ah);
        am = fmaf(Wm[(size_t)(u0 + i) * DD + d], w, am);
    }
    g_ph[blockIdx.y * DD + d] = ah;
    g_pm[blockIdx.y * DD + d] = am;
}

// ---------------------------------------------------------------------------
// Stage 2 (fused): blocks 0..3 fold partials into v_h/v_m; block 4 computes
// g_const = (b_h + b_m) . w_out + b_out.
// ---------------------------------------------------------------------------
__global__ void k_finish(const float* __restrict__ bh,
                         const float* __restrict__ bm,
                         const float* __restrict__ wout,
                         const float* __restrict__ bout) {
    int t = threadIdx.x;
    if (blockIdx.x < 4) {
        int d = blockIdx.x * 256 + t;
        float ah = 0.f, am = 0.f;
#pragma unroll
        for (int c = 0; c < UCHUNKS; ++c) {
            ah += g_ph[c * DD + d];
            am += g_pm[c * DD + d];
        }
        g_vh[d] = ah;
        g_vm[d] = am;
    } else {
        __shared__ float red[8];
        float acc = (bh[t] + bm[t]) * wout[t]
                  + (bh[t + 256] + bm[t + 256]) * wout[t + 256];
#pragma unroll
        for (int o = 16; o > 0; o >>= 1)
            acc += __shfl_down_sync(0xffffffffu, acc, o);
        if ((t & 31) == 0) red[t >> 5] = acc;
        __syncthreads();
        if (t < 8) {
            acc = red[t];
#pragma unroll
            for (int o = 4; o > 0; o >>= 1)
                acc += __shfl_down_sync(0x000000ffu, acc, o);
            if (t == 0) g_const = acc + bout[0];
        }
    }
}

// ---------------------------------------------------------------------------
// Stage 3 (fused row+out pipeline).
//   bids [0, ROW_BLOCKS):   warp-per-row dual dot over x (streaming __ldcs);
//                           publish sH/sM, bump per-batch counter.
//   bids [ROW_BLOCKS, +OUT_BLOCKS): wait for own batch, then write 8 output
//                           rows with __stcs (evict-first -> writebacks drain
//                           now, while DRAM read traffic from later batches
//                           overlaps).
// Out-blocks follow ALL row-blocks in bid order => no deadlock; batch 0
// finishes early so the write stream pipelines behind the read stream.
// ---------------------------------------------------------------------------
__global__ void k_main(const float* __restrict__ x, float* __restrict__ out) {
    int bid = blockIdx.x;
    int t   = threadIdx.x;

    if (bid < ROW_BLOCKS) {
        // ---- producer: dual dot products for 8 rows ----
        int row  = bid * 8 + (t >> 5);
        int lane = t & 31;
        const float4* xr  = reinterpret_cast<const float4*>(x + (size_t)row * DD);
        const float4* vh4 = reinterpret_cast<const float4*>(g_vh);
        const float4* vm4 = reinterpret_cast<const float4*>(g_vm);

        float ah = 0.f, am = 0.f;
#pragma unroll
        for (int i = 0; i < 8; ++i) {
            int idx = lane + 32 * i;
            float4 xv = __ldcs(&xr[idx]);           // read-once, evict-first
            float4 h  = vh4[idx];
            float4 m  = vm4[idx];
            ah = fmaf(xv.x, h.x, fmaf(xv.y, h.y, fmaf(xv.z, h.z, fmaf(xv.w, h.w, ah))));
            am = fmaf(xv.x, m.x, fmaf(xv.y, m.y, fmaf(xv.z, m.z, fmaf(xv.w, m.w, am))));
        }
#pragma unroll
        for (int o = 16; o > 0; o >>= 1) {
            ah += __shfl_xor_sync(0xffffffffu, ah, o);
            am += __shfl_xor_sync(0xffffffffu, am, o);
        }
        if (lane == 0) {
            g_sH[row] = ah;
            g_sM[row] = am;
            __threadfence();                        // release own stores
        }
        __syncthreads();
        if (t == 0) atomicAdd(&g_done[bid >> 7], 1);   // RB_PER_BATCH = 128
    } else {
        // ---- consumer: write 8 output rows of one batch ----
        int ob = bid - ROW_BLOCKS;
        int i0 = ob * 8;            // global row base (b*NN + i)
        int b  = i0 >> 10;          // NN = 1024

        if (t == 0) {
            while (*(volatile int*)&g_done[b] < RB_PER_BATCH)
                __nanosleep(128);
            __threadfence();        // acquire before publishing to block
        }
        __syncthreads();

        float4 m = reinterpret_cast<const float4*>(g_sM + (size_t)b * NN)[t];
        float  c = g_const;
        float4 h0 = reinterpret_cast<const float4*>(g_sH + i0)[0];
        float4 h1 = reinterpret_cast<const float4*>(g_sH + i0)[1];
        float base[8] = {h0.x + c, h0.y + c, h0.z + c, h0.w + c,
                         h1.x + c, h1.y + c, h1.z + c, h1.w + c};
#pragma unroll
        for (int r = 0; r < 8; ++r) {
            __stcs(reinterpret_cast<float4*>(out + (size_t)(i0 + r) * NN) + t,
                   make_float4(base[r] + m.x, base[r] + m.y,
                               base[r] + m.z, base[r] + m.w));
        }
    }
}

extern "C" void kernel_launch(void* const* d_in, const int* in_sizes, int n_in,
                              void* d_out, int out_size) {
    const float* x    = (const float*)d_in[0];
    const float* Wh   = (const float*)d_in[1];
    const float* bh   = (const float*)d_in[2];
    const float* Wm   = (const float*)d_in[3];
    const float* bm   = (const float*)d_in[4];
    const float* wout = (const float*)d_in[5];
    const float* bout = (const float*)d_in[6];
    float* out = (float*)d_out;

    k_zero<<<1, 32>>>();
    k_vec_partial<<<dim3(DD / 128, UCHUNKS), 128>>>(Wh, Wm, wout);
    k_finish<<<5, 256>>>(bh, bm, wout, bout);
    k_main<<<ROW_BLOCKS + OUT_BLOCKS, 256>>>(x, out);
}